// round 5
// baseline (speedup 1.0000x reference)
#include <cuda_runtime.h>
#include <math.h>

#define B_ 16
#define S_ 1024
#define D_ 1024
#define R_ (B_*S_)           // 16384 rows (step-major: r = s*16 + b)
#define CH 16                // steps per chunk
#define NR 256               // rows per chunk
#define NCH 64               // chunks
#define ETA (0.01f * (2.0f/16384.0f))
#define NB 296               // persistent blocks (2 per SM on 148-SM GB300)
#define NT 256               // threads per block
#define SMEMB 17408          // max smem bytes across tile configs

// ---------------- scratch (static device globals, ~233 MB) ----------------
static __device__ float g_b0[R_*D_];        // STATE -> TV -> H2
static __device__ float g_b1[R_*D_];        // H -> RD
static __device__ float g_W [D_*D_];
static __device__ float g_Z [NR*D_];
static __device__ float g_E [NR*D_];
static __device__ float g_T [NCH*NR*NR];    // batched per-chunk 256x256 mats
static __device__ float g_T2[NCH*NR*NR];
static __device__ float g_T4[NCH*NR*NR];
static __device__ float g_Sa[NCH*NR*NR];
static __device__ float g_Sb[NCH*NR*NR];    // final Minv
static __device__ float g_Q [NCH*NR*NR];

static __device__ unsigned g_bar_cnt;
static __device__ unsigned g_bar_phase;

__global__ void reset_kernel() {
    if (threadIdx.x == 0) { g_bar_cnt = 0; g_bar_phase = 0; }
}

__device__ __forceinline__ void gsync(unsigned &ph) {
    __syncthreads();
    if (threadIdx.x == 0) {
        ph++;
        __threadfence();
        unsigned a = atomicAdd(&g_bar_cnt, 1);
        if (a == NB - 1) {
            atomicExch(&g_bar_cnt, 0);
            __threadfence();
            atomicExch(&g_bar_phase, ph);
        } else {
            while (atomicAdd(&g_bar_phase, 0) < ph) __nanosleep(100);
        }
        __threadfence();
    }
    __syncthreads();
}

__device__ __forceinline__ float gelu_exact(float v) {
    return 0.5f*v*(1.0f + erff(v*0.70710678118654752440f));
}

// ---------------- tiled GEMM over a grid-strided tile space ----------------
// C = op(A)@op(B) with optional batch (nb mats, element strides sA/sB/sC/sAux).
// TA: A stored [K,M]; TB: B stored [N,K]. Row-major everywhere.
// epi: 0: C=alpha*acc   1: C+=alpha*acc
//      2: C=acc - A[r,c] + noise[perm(r0+r),c]        (Z build; nb==1)
//      3: T=-eta*strictBL(acc); Sa(aux)=T+I           (mask A)
//      4: C=-eta*inclBL(acc)                          (mask P -> Q)
//      5: C=acc + aux[idx]                            (S-combine)
//      7: C=gelu(C)*acc + RD[perm] + aux2[idx]        (final gate; nb==1)
template<int BM,int BN,int BK,int TM,int TN,bool TA,bool TB>
__device__ void dgemm(char* smraw,
                      const float* __restrict__ A0, int sA, int lda,
                      const float* __restrict__ B0, int sB, int ldb,
                      float* C0, int sC, int ldc,
                      int nb, int M, int N, int K,
                      float alpha, int epi,
                      float* aux, int sAux, const float* __restrict__ aux2, int r0)
{
    float (*As)[BM+4] = (float (*)[BM+4])smraw;
    float (*Bs)[BN+4] = (float (*)[BN+4])(smraw + sizeof(float)*(size_t)BK*(BM+4));
    const int tid = threadIdx.x;
    const int tx = tid % (BN/TN);
    const int ty = tid / (BN/TN);
    const int tpmN = N/BN;
    const int tpm  = (M/BM)*tpmN;
    const int ntiles = nb*tpm;

    for (int t = blockIdx.x; t < ntiles; t += NB) {
        const int cb = t / tpm;
        const int tt = t - cb*tpm;
        const int bm = tt / tpmN;
        const int bn = tt - bm*tpmN;
        const int m0 = bm*BM, n0 = bn*BN;
        const float* A = A0 + (long)cb*sA;
        const float* B = B0 + (long)cb*sB;
        float*       C = C0 + (long)cb*sC;

        float acc[TM][TN];
        #pragma unroll
        for (int i=0;i<TM;i++)
            #pragma unroll
            for (int j=0;j<TN;j++) acc[i][j]=0.f;

        for (int k0 = 0; k0 < K; k0 += BK) {
            #pragma unroll
            for (int it = 0; it < (BM*BK)/NT; it++) {
                int i = tid + it*NT;
                if (!TA) { int mm=i/BK, kk=i-mm*BK; As[kk][mm] = A[(long)(m0+mm)*lda + (k0+kk)]; }
                else     { int kk=i/BM, mm=i-kk*BM; As[kk][mm] = A[(long)(k0+kk)*lda + (m0+mm)]; }
            }
            #pragma unroll
            for (int it = 0; it < (BN*BK)/NT; it++) {
                int i = tid + it*NT;
                if (!TB) { int kk=i/BN, nn=i-kk*BN; Bs[kk][nn] = B[(long)(k0+kk)*ldb + (n0+nn)]; }
                else     { int nn=i/BK, kk=i-nn*BK; Bs[kk][nn] = B[(long)(n0+nn)*ldb + (k0+kk)]; }
            }
            __syncthreads();
            #pragma unroll
            for (int kk=0; kk<BK; kk++) {
                float ra[TM], rb[TN];
                #pragma unroll
                for (int v=0;v<TM;v+=4) *(float4*)&ra[v] = *(const float4*)&As[kk][ty*TM+v];
                #pragma unroll
                for (int v=0;v<TN;v+=4) *(float4*)&rb[v] = *(const float4*)&Bs[kk][tx*TN+v];
                #pragma unroll
                for (int i=0;i<TM;i++)
                    #pragma unroll
                    for (int j=0;j<TN;j++)
                        acc[i][j] += ra[i]*rb[j];
            }
            __syncthreads();
        }

        // ---- epilogue ----
        if (epi == 0) {
            #pragma unroll
            for (int i=0;i<TM;i++){ long rb_=(long)(m0+ty*TM+i)*ldc;
                #pragma unroll
                for (int j=0;j<TN;j++) C[rb_ + n0+tx*TN+j] = alpha*acc[i][j]; }
        } else if (epi == 1) {
            #pragma unroll
            for (int i=0;i<TM;i++){ long rb_=(long)(m0+ty*TM+i)*ldc;
                #pragma unroll
                for (int j=0;j<TN;j++) C[rb_ + n0+tx*TN+j] += alpha*acc[i][j]; }
        } else if (epi == 2) {
            #pragma unroll
            for (int i=0;i<TM;i++){
                int r = m0+ty*TM+i; int gr = r0 + r; int s = gr>>4, b = gr&15;
                long rb_=(long)r*ldc; long nbs=((long)b*S_+s)*D_;
                #pragma unroll
                for (int j=0;j<TN;j++){ int c = n0+tx*TN+j;
                    C[rb_+c] = acc[i][j] - A[(long)r*lda + c] + aux2[nbs + c]; } }
        } else if (epi == 3) {
            float* Sa = aux + (long)cb*sAux;
            #pragma unroll
            for (int i=0;i<TM;i++){ int r = m0+ty*TM+i; long rb_=(long)r*ldc;
                #pragma unroll
                for (int j=0;j<TN;j++){ int c = n0+tx*TN+j;
                    float tv = ((r>>4)>(c>>4)) ? (-ETA)*acc[i][j] : 0.f;
                    C[rb_+c] = tv; Sa[rb_+c] = tv + ((r==c)?1.f:0.f); } }
        } else if (epi == 4) {
            #pragma unroll
            for (int i=0;i<TM;i++){ int r = m0+ty*TM+i; long rb_=(long)r*ldc;
                #pragma unroll
                for (int j=0;j<TN;j++){ int c = n0+tx*TN+j;
                    C[rb_+c] = ((r>>4)>=(c>>4)) ? (-ETA)*acc[i][j] : 0.f; } }
        } else if (epi == 5) {
            const float* Dq = aux + (long)cb*sAux;
            #pragma unroll
            for (int i=0;i<TM;i++){ long rb_=(long)(m0+ty*TM+i)*ldc;
                #pragma unroll
                for (int j=0;j<TN;j++){ long idx = rb_ + n0+tx*TN+j;
                    C[idx] = acc[i][j] + Dq[idx]; } }
        } else { // epi == 7
            #pragma unroll
            for (int i=0;i<TM;i++){
                int r = m0+ty*TM+i; int b = r/S_, s = r - b*S_;
                long rb_=(long)r*ldc; long rdb=((long)(s*16+b))*D_;
                #pragma unroll
                for (int j=0;j<TN;j++){ int c = n0+tx*TN+j; long idx = rb_+c;
                    float u = C[idx];
                    C[idx] = gelu_exact(u)*acc[i][j] + g_b1[rdb + c] + aux2[idx]; } }
        }
    }
}

#define DG_BIG dgemm<128,128,16,8,8,false,true>
#define DG_CNT dgemm<64,64,32,4,4,false,true>
#define DG_CNN dgemm<64,64,32,4,4,false,false>
#define DG_CTN dgemm<64,64,32,4,4,true,false>

// ---------------- the mega-kernel ----------------
__global__ void __launch_bounds__(NT, 2)
mega(const float* __restrict__ x, const float* __restrict__ noise,
     const float* __restrict__ alpha1, const float* __restrict__ alpha2,
     const float* __restrict__ Wmap, const float* __restrict__ Wstate,
     const float* __restrict__ Wprobe, const float* __restrict__ Wp1,
     const float* __restrict__ Wp2, float* __restrict__ out)
{
    __shared__ __align__(16) char sm[SMEMB];
    unsigned ph = 0;
    const long tstep = (long)NB*NT;
    const long gt0 = (long)blockIdx.x*NT + threadIdx.x;

    // ph0: W copy + H = tanh(alpha1*x) (step-major permuted)
    for (long g = gt0; g < (long)D_*D_/4; g += tstep)
        *(float4*)(g_W + g*4) = *(const float4*)(Wmap + g*4);
    for (long g = gt0; g < (long)R_*D_/4; g += tstep) {
        int d4 = (int)(g % (D_/4)); int r = (int)(g / (D_/4));
        int s = r >> 4, b = r & 15;
        float4 xv = *(const float4*)(x + ((long)b*S_ + s)*D_ + (long)d4*4);
        float4 a  = *(const float4*)(alpha1 + (long)d4*4);
        float4 h;
        h.x = tanhf(a.x*xv.x); h.y = tanhf(a.y*xv.y);
        h.z = tanhf(a.z*xv.z); h.w = tanhf(a.w*xv.w);
        *(float4*)(g_b1 + (long)r*D_ + (long)d4*4) = h;
    }
    gsync(ph);

    // ph1: STATE = H@Ws^T -> b0 ; PROBE = H@Wp^T -> out
    DG_BIG(sm, g_b1,0,D_, Wstate,0,D_, g_b0,0,D_, 1, R_,D_,D_, 1.f, 0, nullptr,0,nullptr,0);
    DG_BIG(sm, g_b1,0,D_, Wprobe,0,D_, out, 0,D_, 1, R_,D_,D_, 1.f, 0, nullptr,0,nullptr,0);
    gsync(ph);

    // ph2: TV = STATE + noise (permuted), in place
    for (long g = gt0; g < (long)R_*D_/4; g += tstep) {
        int d4 = (int)(g % (D_/4)); int r = (int)(g / (D_/4));
        int s = r >> 4, b = r & 15;
        float4 st = *(const float4*)(g_b0 + (long)r*D_ + (long)d4*4);
        float4 nz = *(const float4*)(noise + ((long)b*S_ + s)*D_ + (long)d4*4);
        st.x += nz.x; st.y += nz.y; st.z += nz.z; st.w += nz.w;
        *(float4*)(g_b0 + (long)r*D_ + (long)d4*4) = st;
    }
    gsync(ph);

    // ph3 (batched over 64 chunks): A=TV@TV^T -> T,Sa(masked);  P=PROBE@TV^T -> Q(masked)
    DG_CNT(sm, g_b0,NR*D_,D_, g_b0,NR*D_,D_, g_T,NR*NR,NR, NCH, NR,NR,D_, 1.f, 3, g_Sa,NR*NR, nullptr,0);
    DG_CNT(sm, out, NR*D_,D_, g_b0,NR*D_,D_, g_Q,NR*NR,NR, NCH, NR,NR,D_, 1.f, 4, nullptr,0, nullptr,0);
    gsync(ph);

    // Minv = (I+T)(I+T^2)(I+T^4)(I+T^8), batched (exact: T^16 = 0)
    DG_CNN(sm, g_T,NR*NR,NR, g_T,NR*NR,NR, g_T2,NR*NR,NR, NCH, NR,NR,NR, 1.f, 0, nullptr,0,nullptr,0);   // T2
    gsync(ph);
    DG_CNN(sm, g_Sa,NR*NR,NR, g_T2,NR*NR,NR, g_Sb,NR*NR,NR, NCH, NR,NR,NR, 1.f, 5, g_Sa,NR*NR, nullptr,0); // Sb=Sa(I+T2)
    DG_CNN(sm, g_T2,NR*NR,NR, g_T2,NR*NR,NR, g_T4,NR*NR,NR, NCH, NR,NR,NR, 1.f, 0, nullptr,0,nullptr,0);   // T4
    gsync(ph);
    DG_CNN(sm, g_Sb,NR*NR,NR, g_T4,NR*NR,NR, g_Sa,NR*NR,NR, NCH, NR,NR,NR, 1.f, 5, g_Sb,NR*NR, nullptr,0); // Sa=Sb(I+T4)
    DG_CNN(sm, g_T4,NR*NR,NR, g_T4,NR*NR,NR, g_T2,NR*NR,NR, NCH, NR,NR,NR, 1.f, 0, nullptr,0,nullptr,0);   // T8 (in T2)
    gsync(ph);
    DG_CNN(sm, g_Sa,NR*NR,NR, g_T2,NR*NR,NR, g_Sb,NR*NR,NR, NCH, NR,NR,NR, 1.f, 5, g_Sa,NR*NR, nullptr,0); // Minv in Sb
    gsync(ph);

    // Sequential W-dependent loop: 3 phases per chunk
    for (int c = 0; c < NCH; c++) {
        const int off = c*NR*D_, bo = c*NR*NR;
        // ph_a: Z = TVc@W^T - TVc + noise_c ; RDbase = PROBEc@W^T
        DG_CNT(sm, g_b0+off,0,D_, g_W,0,D_, g_Z,0,D_, 1, NR,D_,D_, 1.f, 2, nullptr,0, noise, c*NR);
        DG_CNT(sm, out+off, 0,D_, g_W,0,D_, g_b1+off,0,D_, 1, NR,D_,D_, 1.f, 0, nullptr,0,nullptr,0);
        gsync(ph);
        // ph_b: E = Minv_c @ Z
        DG_CNN(sm, g_Sb+bo,0,NR, g_Z,0,D_, g_E,0,D_, 1, NR,D_,NR, 1.f, 0, nullptr,0,nullptr,0);
        gsync(ph);
        // ph_c: RD += Q_c @ E ; W += -eta * E^T @ TVc
        DG_CNN(sm, g_Q+bo,0,NR, g_E,0,D_, g_b1+off,0,D_, 1, NR,D_,NR, 1.f, 1, nullptr,0,nullptr,0);
        DG_CTN(sm, g_E,0,D_, g_b0+off,0,D_, g_W,0,D_, 1, D_,D_,NR, -ETA, 1, nullptr,0,nullptr,0);
        gsync(ph);
    }

    // ph8: H2 = tanh(alpha2*(RD[perm] + x)) -> b0 (row-major r = b*S+s)
    for (long g = gt0; g < (long)R_*D_/4; g += tstep) {
        int d4 = (int)(g % (D_/4)); int r = (int)(g / (D_/4));
        int b = r / S_, s = r - b*S_;
        float4 rd = *(const float4*)(g_b1 + ((long)(s*16+b))*D_ + (long)d4*4);
        float4 xv = *(const float4*)(x + (long)r*D_ + (long)d4*4);
        float4 a2 = *(const float4*)(alpha2 + (long)d4*4);
        float4 h2;
        h2.x = tanhf(a2.x*(rd.x+xv.x)); h2.y = tanhf(a2.y*(rd.y+xv.y));
        h2.z = tanhf(a2.z*(rd.z+xv.z)); h2.w = tanhf(a2.w*(rd.w+xv.w));
        *(float4*)(g_b0 + (long)r*D_ + (long)d4*4) = h2;
    }
    gsync(ph);

    // ph9: U = H2@Wp1^T -> out
    DG_BIG(sm, g_b0,0,D_, Wp1,0,D_, out,0,D_, 1, R_,D_,D_, 1.f, 0, nullptr,0,nullptr,0);
    gsync(ph);

    // ph10: out = gelu(U) * (H2@Wp2^T) + RD[perm] + x
    DG_BIG(sm, g_b0,0,D_, Wp2,0,D_, out,0,D_, 1, R_,D_,D_, 1.f, 7, nullptr,0, x, 0);
}

extern "C" void kernel_launch(void* const* d_in, const int* in_sizes, int n_in,
                              void* d_out, int out_size) {
    const float* x       = (const float*)d_in[0];
    const float* noise   = (const float*)d_in[1];
    const float* alpha1  = (const float*)d_in[2];
    const float* alpha2  = (const float*)d_in[3];
    const float* W_map   = (const float*)d_in[4];
    const float* W_state = (const float*)d_in[5];
    const float* W_probe = (const float*)d_in[6];
    const float* W_p1    = (const float*)d_in[7];
    const float* W_p2    = (const float*)d_in[8];
    float* out = (float*)d_out;

    reset_kernel<<<1, 32>>>();
    mega<<<NB, NT>>>(x, noise, alpha1, alpha2, W_map, W_state, W_probe, W_p1, W_p2, out);
}

// round 7
// speedup vs baseline: 1.0021x; 1.0021x over previous
#include <cuda_runtime.h>
#include <math.h>

#define B_ 16
#define S_ 1024
#define D_ 1024
#define R_ (B_*S_)           // 16384 rows (step-major: r = s*16 + b)
#define CH 16                // steps per chunk
#define NR 256               // rows per chunk
#define NCH 64               // chunks
#define ETA (0.01f * (2.0f/16384.0f))
#define NB 296               // persistent blocks (2 per SM on 148-SM GB300)
#define NT 256               // threads per block
#define SMEMB 17408          // max smem bytes across tile configs

// ---------------- scratch (static device globals, ~233 MB) ----------------
static __device__ float g_b0[R_*D_];        // STATE -> TV -> H2
static __device__ float g_b1[R_*D_];        // H -> RD
static __device__ float g_W [D_*D_];
static __device__ float g_Z [NR*D_];
static __device__ float g_E [NR*D_];
static __device__ float g_T [NCH*NR*NR];    // batched per-chunk 256x256 mats
static __device__ float g_T2[NCH*NR*NR];
static __device__ float g_T4[NCH*NR*NR];
static __device__ float g_Sa[NCH*NR*NR];
static __device__ float g_Sb[NCH*NR*NR];    // final Minv
static __device__ float g_Q [NCH*NR*NR];

static __device__ unsigned g_bar_cnt;
static __device__ unsigned g_bar_phase;

__global__ void reset_kernel() {
    if (threadIdx.x == 0) { g_bar_cnt = 0; g_bar_phase = 0; }
}

__device__ __forceinline__ void gsync(unsigned &ph) {
    __syncthreads();
    if (threadIdx.x == 0) {
        ph++;
        __threadfence();
        unsigned a = atomicAdd(&g_bar_cnt, 1);
        if (a == NB - 1) {
            atomicExch(&g_bar_cnt, 0);
            __threadfence();
            atomicExch(&g_bar_phase, ph);
        } else {
            while (atomicAdd(&g_bar_phase, 0) < ph) __nanosleep(100);
        }
        __threadfence();
    }
    __syncthreads();
}

__device__ __forceinline__ float gelu_exact(float v) {
    return 0.5f*v*(1.0f + erff(v*0.70710678118654752440f));
}

// ---------------- tiled GEMM over a grid-strided tile space ----------------
// C = op(A)@op(B) with optional batch (nb mats, element strides sA/sB/sC/sAux).
// TA: A stored [K,M]; TB: B stored [N,K]. Row-major everywhere.
// epi: 0: C=alpha*acc   1: C+=alpha*acc
//      2: C=acc - A[r,c] + noise[perm(r0+r),c]        (Z build; nb==1)
//      3: T=-eta*strictBL(acc); Sa(aux)=T+I           (mask A)
//      4: C=-eta*inclBL(acc)                          (mask P -> Q)
//      5: C=acc + aux[idx]                            (S-combine)
//      7: C=gelu(C)*acc + RD[perm] + aux2[idx]        (final gate; nb==1)
template<int BM,int BN,int BK,int TM,int TN,bool TA,bool TB>
__device__ void dgemm(char* smraw,
                      const float* __restrict__ A0, int sA, int lda,
                      const float* __restrict__ B0, int sB, int ldb,
                      float* C0, int sC, int ldc,
                      int nb, int M, int N, int K,
                      float alpha, int epi,
                      float* aux, int sAux, const float* __restrict__ aux2, int r0)
{
    float (*As)[BM+4] = (float (*)[BM+4])smraw;
    float (*Bs)[BN+4] = (float (*)[BN+4])(smraw + sizeof(float)*(size_t)BK*(BM+4));
    const int tid = threadIdx.x;
    const int tx = tid % (BN/TN);
    const int ty = tid / (BN/TN);
    const int tpmN = N/BN;
    const int tpm  = (M/BM)*tpmN;
    const int ntiles = nb*tpm;

    for (int t = blockIdx.x; t < ntiles; t += NB) {
        const int cb = t / tpm;
        const int tt = t - cb*tpm;
        const int bm = tt / tpmN;
        const int bn = tt - bm*tpmN;
        const int m0 = bm*BM, n0 = bn*BN;
        const float* A = A0 + (long)cb*sA;
        const float* B = B0 + (long)cb*sB;
        float*       C = C0 + (long)cb*sC;

        float acc[TM][TN];
        #pragma unroll
        for (int i=0;i<TM;i++)
            #pragma unroll
            for (int j=0;j<TN;j++) acc[i][j]=0.f;

        for (int k0 = 0; k0 < K; k0 += BK) {
            #pragma unroll
            for (int it = 0; it < (BM*BK)/NT; it++) {
                int i = tid + it*NT;
                if (!TA) { int mm=i/BK, kk=i-mm*BK; As[kk][mm] = A[(long)(m0+mm)*lda + (k0+kk)]; }
                else     { int kk=i/BM, mm=i-kk*BM; As[kk][mm] = A[(long)(k0+kk)*lda + (m0+mm)]; }
            }
            #pragma unroll
            for (int it = 0; it < (BN*BK)/NT; it++) {
                int i = tid + it*NT;
                if (!TB) { int kk=i/BN, nn=i-kk*BN; Bs[kk][nn] = B[(long)(k0+kk)*ldb + (n0+nn)]; }
                else     { int nn=i/BK, kk=i-nn*BK; Bs[kk][nn] = B[(long)(n0+nn)*ldb + (k0+kk)]; }
            }
            __syncthreads();
            #pragma unroll
            for (int kk=0; kk<BK; kk++) {
                float ra[TM], rb[TN];
                #pragma unroll
                for (int v=0;v<TM;v+=4) *(float4*)&ra[v] = *(const float4*)&As[kk][ty*TM+v];
                #pragma unroll
                for (int v=0;v<TN;v+=4) *(float4*)&rb[v] = *(const float4*)&Bs[kk][tx*TN+v];
                #pragma unroll
                for (int i=0;i<TM;i++)
                    #pragma unroll
                    for (int j=0;j<TN;j++)
                        acc[i][j] += ra[i]*rb[j];
            }
            __syncthreads();
        }

        // ---- epilogue ----
        if (epi == 0) {
            #pragma unroll
            for (int i=0;i<TM;i++){ long rb_=(long)(m0+ty*TM+i)*ldc;
                #pragma unroll
                for (int j=0;j<TN;j++) C[rb_ + n0+tx*TN+j] = alpha*acc[i][j]; }
        } else if (epi == 1) {
            #pragma unroll
            for (int i=0;i<TM;i++){ long rb_=(long)(m0+ty*TM+i)*ldc;
                #pragma unroll
                for (int j=0;j<TN;j++) C[rb_ + n0+tx*TN+j] += alpha*acc[i][j]; }
        } else if (epi == 2) {
            #pragma unroll
            for (int i=0;i<TM;i++){
                int r = m0+ty*TM+i; int gr = r0 + r; int s = gr>>4, b = gr&15;
                long rb_=(long)r*ldc; long nbs=((long)b*S_+s)*D_;
                #pragma unroll
                for (int j=0;j<TN;j++){ int c = n0+tx*TN+j;
                    C[rb_+c] = acc[i][j] - A[(long)r*lda + c] + aux2[nbs + c]; } }
        } else if (epi == 3) {
            float* Sa = aux + (long)cb*sAux;
            #pragma unroll
            for (int i=0;i<TM;i++){ int r = m0+ty*TM+i; long rb_=(long)r*ldc;
                #pragma unroll
                for (int j=0;j<TN;j++){ int c = n0+tx*TN+j;
                    float tv = ((r>>4)>(c>>4)) ? (-ETA)*acc[i][j] : 0.f;
                    C[rb_+c] = tv; Sa[rb_+c] = tv + ((r==c)?1.f:0.f); } }
        } else if (epi == 4) {
            #pragma unroll
            for (int i=0;i<TM;i++){ int r = m0+ty*TM+i; long rb_=(long)r*ldc;
                #pragma unroll
                for (int j=0;j<TN;j++){ int c = n0+tx*TN+j;
                    C[rb_+c] = ((r>>4)>=(c>>4)) ? (-ETA)*acc[i][j] : 0.f; } }
        } else if (epi == 5) {
            const float* Dq = aux + (long)cb*sAux;
            #pragma unroll
            for (int i=0;i<TM;i++){ long rb_=(long)(m0+ty*TM+i)*ldc;
                #pragma unroll
                for (int j=0;j<TN;j++){ long idx = rb_ + n0+tx*TN+j;
                    C[idx] = acc[i][j] + Dq[idx]; } }
        } else { // epi == 7
            #pragma unroll
            for (int i=0;i<TM;i++){
                int r = m0+ty*TM+i; int b = r/S_, s = r - b*S_;
                long rb_=(long)r*ldc; long rdb=((long)(s*16+b))*D_;
                #pragma unroll
                for (int j=0;j<TN;j++){ int c = n0+tx*TN+j; long idx = rb_+c;
                    float u = C[idx];
                    C[idx] = gelu_exact(u)*acc[i][j] + g_b1[rdb + c] + aux2[idx]; } }
        }
    }
}

#define DG_BIG dgemm<128,128,16,8,8,false,true>
#define DG_CNT dgemm<64,64,32,4,4,false,true>
#define DG_CNN dgemm<64,64,32,4,4,false,false>
#define DG_CTN dgemm<64,64,32,4,4,true,false>

// ---------------- the mega-kernel ----------------
__global__ void __launch_bounds__(NT, 2)
mega(const float* __restrict__ x, const float* __restrict__ noise,
     const float* __restrict__ alpha1, const float* __restrict__ alpha2,
     const float* __restrict__ Wmap, const float* __restrict__ Wstate,
     const float* __restrict__ Wprobe, const float* __restrict__ Wp1,
     const float* __restrict__ Wp2, float* __restrict__ out)
{
    __shared__ __align__(16) char sm[SMEMB];
    unsigned ph = 0;
    const long tstep = (long)NB*NT;
    const long gt0 = (long)blockIdx.x*NT + threadIdx.x;

    // ph0: W copy + H = tanh(alpha1*x) (step-major permuted)
    for (long g = gt0; g < (long)D_*D_/4; g += tstep)
        *(float4*)(g_W + g*4) = *(const float4*)(Wmap + g*4);
    for (long g = gt0; g < (long)R_*D_/4; g += tstep) {
        int d4 = (int)(g % (D_/4)); int r = (int)(g / (D_/4));
        int s = r >> 4, b = r & 15;
        float4 xv = *(const float4*)(x + ((long)b*S_ + s)*D_ + (long)d4*4);
        float4 a  = *(const float4*)(alpha1 + (long)d4*4);
        float4 h;
        h.x = tanhf(a.x*xv.x); h.y = tanhf(a.y*xv.y);
        h.z = tanhf(a.z*xv.z); h.w = tanhf(a.w*xv.w);
        *(float4*)(g_b1 + (long)r*D_ + (long)d4*4) = h;
    }
    gsync(ph);

    // ph1: STATE = H@Ws^T -> b0 ; PROBE = H@Wp^T -> out
    DG_BIG(sm, g_b1,0,D_, Wstate,0,D_, g_b0,0,D_, 1, R_,D_,D_, 1.f, 0, nullptr,0,nullptr,0);
    DG_BIG(sm, g_b1,0,D_, Wprobe,0,D_, out, 0,D_, 1, R_,D_,D_, 1.f, 0, nullptr,0,nullptr,0);
    gsync(ph);

    // ph2: TV = STATE + noise (permuted), in place
    for (long g = gt0; g < (long)R_*D_/4; g += tstep) {
        int d4 = (int)(g % (D_/4)); int r = (int)(g / (D_/4));
        int s = r >> 4, b = r & 15;
        float4 st = *(const float4*)(g_b0 + (long)r*D_ + (long)d4*4);
        float4 nz = *(const float4*)(noise + ((long)b*S_ + s)*D_ + (long)d4*4);
        st.x += nz.x; st.y += nz.y; st.z += nz.z; st.w += nz.w;
        *(float4*)(g_b0 + (long)r*D_ + (long)d4*4) = st;
    }
    gsync(ph);

    // ph3 (batched over 64 chunks): A=TV@TV^T -> T,Sa(masked);  P=PROBE@TV^T -> Q(masked)
    DG_CNT(sm, g_b0,NR*D_,D_, g_b0,NR*D_,D_, g_T,NR*NR,NR, NCH, NR,NR,D_, 1.f, 3, g_Sa,NR*NR, nullptr,0);
    DG_CNT(sm, out, NR*D_,D_, g_b0,NR*D_,D_, g_Q,NR*NR,NR, NCH, NR,NR,D_, 1.f, 4, nullptr,0, nullptr,0);
    gsync(ph);

    // Minv = (I+T)(I+T^2)(I+T^4)(I+T^8), batched (exact: T^16 = 0)
    DG_CNN(sm, g_T,NR*NR,NR, g_T,NR*NR,NR, g_T2,NR*NR,NR, NCH, NR,NR,NR, 1.f, 0, nullptr,0,nullptr,0);   // T2
    gsync(ph);
    DG_CNN(sm, g_Sa,NR*NR,NR, g_T2,NR*NR,NR, g_Sb,NR*NR,NR, NCH, NR,NR,NR, 1.f, 5, g_Sa,NR*NR, nullptr,0); // Sb=Sa(I+T2)
    DG_CNN(sm, g_T2,NR*NR,NR, g_T2,NR*NR,NR, g_T4,NR*NR,NR, NCH, NR,NR,NR, 1.f, 0, nullptr,0,nullptr,0);   // T4
    gsync(ph);
    DG_CNN(sm, g_Sb,NR*NR,NR, g_T4,NR*NR,NR, g_Sa,NR*NR,NR, NCH, NR,NR,NR, 1.f, 5, g_Sb,NR*NR, nullptr,0); // Sa=Sb(I+T4)
    DG_CNN(sm, g_T4,NR*NR,NR, g_T4,NR*NR,NR, g_T2,NR*NR,NR, NCH, NR,NR,NR, 1.f, 0, nullptr,0,nullptr,0);   // T8 (in T2)
    gsync(ph);
    DG_CNN(sm, g_Sa,NR*NR,NR, g_T2,NR*NR,NR, g_Sb,NR*NR,NR, NCH, NR,NR,NR, 1.f, 5, g_Sa,NR*NR, nullptr,0); // Minv in Sb
    gsync(ph);

    // Sequential W-dependent loop: 3 phases per chunk
    for (int c = 0; c < NCH; c++) {
        const int off = c*NR*D_, bo = c*NR*NR;
        // ph_a: Z = TVc@W^T - TVc + noise_c ; RDbase = PROBEc@W^T
        DG_CNT(sm, g_b0+off,0,D_, g_W,0,D_, g_Z,0,D_, 1, NR,D_,D_, 1.f, 2, nullptr,0, noise, c*NR);
        DG_CNT(sm, out+off, 0,D_, g_W,0,D_, g_b1+off,0,D_, 1, NR,D_,D_, 1.f, 0, nullptr,0,nullptr,0);
        gsync(ph);
        // ph_b: E = Minv_c @ Z
        DG_CNN(sm, g_Sb+bo,0,NR, g_Z,0,D_, g_E,0,D_, 1, NR,D_,NR, 1.f, 0, nullptr,0,nullptr,0);
        gsync(ph);
        // ph_c: RD += Q_c @ E ; W += -eta * E^T @ TVc
        DG_CNN(sm, g_Q+bo,0,NR, g_E,0,D_, g_b1+off,0,D_, 1, NR,D_,NR, 1.f, 1, nullptr,0,nullptr,0);
        DG_CTN(sm, g_E,0,D_, g_b0+off,0,D_, g_W,0,D_, 1, D_,D_,NR, -ETA, 1, nullptr,0,nullptr,0);
        gsync(ph);
    }

    // ph8: H2 = tanh(alpha2*(RD[perm] + x)) -> b0 (row-major r = b*S+s)
    for (long g = gt0; g < (long)R_*D_/4; g += tstep) {
        int d4 = (int)(g % (D_/4)); int r = (int)(g / (D_/4));
        int b = r / S_, s = r - b*S_;
        float4 rd = *(const float4*)(g_b1 + ((long)(s*16+b))*D_ + (long)d4*4);
        float4 xv = *(const float4*)(x + (long)r*D_ + (long)d4*4);
        float4 a2 = *(const float4*)(alpha2 + (long)d4*4);
        float4 h2;
        h2.x = tanhf(a2.x*(rd.x+xv.x)); h2.y = tanhf(a2.y*(rd.y+xv.y));
        h2.z = tanhf(a2.z*(rd.z+xv.z)); h2.w = tanhf(a2.w*(rd.w+xv.w));
        *(float4*)(g_b0 + (long)r*D_ + (long)d4*4) = h2;
    }
    gsync(ph);

    // ph9: U = H2@Wp1^T -> out
    DG_BIG(sm, g_b0,0,D_, Wp1,0,D_, out,0,D_, 1, R_,D_,D_, 1.f, 0, nullptr,0,nullptr,0);
    gsync(ph);

    // ph10: out = gelu(U) * (H2@Wp2^T) + RD[perm] + x
    DG_BIG(sm, g_b0,0,D_, Wp2,0,D_, out,0,D_, 1, R_,D_,D_, 1.f, 7, nullptr,0, x, 0);
}

extern "C" void kernel_launch(void* const* d_in, const int* in_sizes, int n_in,
                              void* d_out, int out_size) {
    const float* x       = (const float*)d_in[0];
    const float* noise   = (const float*)d_in[1];
    const float* alpha1  = (const float*)d_in[2];
    const float* alpha2  = (const float*)d_in[3];
    const float* W_map   = (const float*)d_in[4];
    const float* W_state = (const float*)d_in[5];
    const float* W_probe = (const float*)d_in[6];
    const float* W_p1    = (const float*)d_in[7];
    const float* W_p2    = (const float*)d_in[8];
    float* out = (float*)d_out;

    reset_kernel<<<1, 32>>>();
    mega<<<NB, NT>>>(x, noise, alpha1, alpha2, W_map, W_state, W_probe, W_p1, W_p2, out);
}